// round 14
// baseline (speedup 1.0000x reference)
#include <cuda_runtime.h>
#include <cuda_fp16.h>
#include <cstdint>

// ============================================================================
// Problem sizes
// ============================================================================
#define TOKENS 8192
#define D_IN   4096
#define D_OUT  4096

// Scratch (device globals; no allocations allowed)
__device__ __half g_A[(size_t)TOKENS * D_IN];   // 64 MB: x in fp16
__device__ __half g_B[(size_t)D_OUT  * D_IN];   // 32 MB: W in fp16 (exact)

// ============================================================================
// GEMM configuration: CTA 128x128x64, 256 threads, 2 CTAs/SM
// ============================================================================
constexpr int M_TILE = 128;
constexpr int N_TILE = 128;
constexpr int K_TILE = 64;                 // 64 fp16 = 128 B rows
constexpr int STAGES = 3;
constexpr int NUM_K  = D_IN / K_TILE;      // 64
constexpr int THREADS = 256;               // 8 warps: 2(m) x 4(n), warp tile 64x32

constexpr int A_BYTES = M_TILE * 128;      // 16 KB
constexpr int B_BYTES = N_TILE * 128;      // 16 KB
constexpr int STAGE_BYTES = A_BYTES + B_BYTES;     // 32 KB
constexpr int SMEM_BARS  = 0;              // full[s]=s*16, empty[s]=s*16+8
constexpr int SMEM_TILES = 1024;
constexpr int SMEM_TOTAL = SMEM_TILES + STAGES * STAGE_BYTES;  // 99328 -> 2 CTAs/SM

// ============================================================================
// Prep kernel: branch-free W and X loops, 32 B/iteration for MLP=2.
// ============================================================================
constexpr size_t W_PAIRS = (size_t)D_OUT * D_IN / 8;    // 2x int4 per iter
constexpr size_t X_PAIRS = (size_t)TOKENS * D_IN / 8;   // 2x float4 per iter

__global__ void prep_kernel(const float* __restrict__ x, const int* __restrict__ wq) {
    const size_t nth = (size_t)gridDim.x * blockDim.x;
    const size_t t0 = (size_t)blockIdx.x * blockDim.x + threadIdx.x;

    for (size_t i = t0; i < W_PAIRS; i += nth) {
        int4 v0 = __ldcs(reinterpret_cast<const int4*>(wq) + i * 2);
        int4 v1 = __ldcs(reinterpret_cast<const int4*>(wq) + i * 2 + 1);
        __half2 a0 = __floats2half2_rn((float)v0.x, (float)v0.y);  // int8 exact in fp16
        __half2 a1 = __floats2half2_rn((float)v0.z, (float)v0.w);
        __half2 a2 = __floats2half2_rn((float)v1.x, (float)v1.y);
        __half2 a3 = __floats2half2_rn((float)v1.z, (float)v1.w);
        uint4 pk;
        pk.x = *reinterpret_cast<uint32_t*>(&a0);
        pk.y = *reinterpret_cast<uint32_t*>(&a1);
        pk.z = *reinterpret_cast<uint32_t*>(&a2);
        pk.w = *reinterpret_cast<uint32_t*>(&a3);
        *reinterpret_cast<uint4*>(&g_B[i * 8]) = pk;
    }
    for (size_t j = t0; j < X_PAIRS; j += nth) {
        float4 v0 = __ldcs(reinterpret_cast<const float4*>(x) + j * 2);
        float4 v1 = __ldcs(reinterpret_cast<const float4*>(x) + j * 2 + 1);
        __half2 a0 = __floats2half2_rn(v0.x, v0.y);
        __half2 a1 = __floats2half2_rn(v0.z, v0.w);
        __half2 a2 = __floats2half2_rn(v1.x, v1.y);
        __half2 a3 = __floats2half2_rn(v1.z, v1.w);
        uint4 pk;
        pk.x = *reinterpret_cast<uint32_t*>(&a0);
        pk.y = *reinterpret_cast<uint32_t*>(&a1);
        pk.z = *reinterpret_cast<uint32_t*>(&a2);
        pk.w = *reinterpret_cast<uint32_t*>(&a3);
        *reinterpret_cast<uint4*>(&g_A[j * 8]) = pk;
    }
}

// ============================================================================
// PTX helpers
// ============================================================================
__device__ __forceinline__ uint32_t smem_u32(const void* p) {
    uint32_t a;
    asm("{ .reg .u64 t; cvta.to.shared.u64 t, %1; cvt.u32.u64 %0, t; }"
        : "=r"(a) : "l"(p));
    return a;
}

__device__ __forceinline__ void cp_async16(uint32_t dst, const void* src) {
    asm volatile("cp.async.cg.shared.global [%0], [%1], 16;"
                 :: "r"(dst), "l"(src) : "memory");
}

#define MBARRIER_INIT(addr, cnt) \
    asm volatile("mbarrier.init.shared.b64 [%0], %1;" \
                 :: "r"((uint32_t)(addr)), "r"((uint32_t)(cnt)) : "memory")

#define MBARRIER_ARRIVE(addr) \
    asm volatile("mbarrier.arrive.shared.b64 _, [%0];" \
                 :: "r"((uint32_t)(addr)) : "memory")

// Each thread's outstanding cp.asyncs arrive (count 1) on the mbarrier when
// they ALL complete; .noinc counts against the barrier's init count.
#define CP_ASYNC_MBAR_ARRIVE_NOINC(addr) \
    asm volatile("cp.async.mbarrier.arrive.noinc.shared.b64 [%0];" \
                 :: "r"((uint32_t)(addr)) : "memory")

// Non-blocking single probe: acquire try_wait -> 0/1 predicate in a register.
// Issue early, consume late: the ~90cyc result latency overlaps useful work.
#define MBARRIER_TRY_ONCE(dst, mbar_smem_addr, phase_parity) \
    asm volatile( \
        "{\n\t" \
        ".reg .pred p;\n\t" \
        "mbarrier.try_wait.parity.acquire.cta.shared::cta.b64 p, [%1], %2;\n\t" \
        "selp.b32 %0, 1, 0, p;\n\t" \
        "}" \
        : "=r"(dst) : "r"((uint32_t)(mbar_smem_addr)), "r"((uint32_t)(phase_parity)) \
        : "memory")

// Spin until ready (used only when the early probe missed).
#define MBARRIER_SPIN(mbar_smem_addr, phase_parity) \
    asm volatile( \
        "{\n\t" \
        ".reg .pred P1;\n\t" \
        "WAIT_LOOP_%=:\n\t" \
        "mbarrier.try_wait.parity.acquire.cta.shared::cta.b64 P1, [%0], %1, 0x989680;\n\t" \
        "@P1 bra.uni WAIT_DONE_%=;\n\t" \
        "bra.uni WAIT_LOOP_%=;\n\t" \
        "WAIT_DONE_%=:\n\t" \
        "}" \
        :: "r"((uint32_t)(mbar_smem_addr)), "r"((uint32_t)(phase_parity)) : "memory")

#define MBARRIER_WAIT_PARITY(mbar_smem_addr, phase_parity) do { \
    uint32_t _done; \
    MBARRIER_TRY_ONCE(_done, mbar_smem_addr, phase_parity); \
    if (!_done) MBARRIER_SPIN(mbar_smem_addr, phase_parity); \
} while (0)

// Relaxed wait: safe ONLY when all post-wait accesses are async-proxy
// (cp.async issues) — the producer path here.
#define MBARRIER_WAIT_PARITY_RELAXED(mbar_smem_addr, phase_parity) do { \
    uint32_t _mbar = (uint32_t)(mbar_smem_addr); \
    uint32_t _parity = (uint32_t)(phase_parity); \
    uint32_t _done; \
    asm volatile( \
        "{\n\t" \
        ".reg .pred p;\n\t" \
        "mbarrier.try_wait.parity.relaxed.cta.shared::cta.b64 p, [%1], %2;\n\t" \
        "selp.b32 %0, 1, 0, p;\n\t" \
        "}" \
        : "=r"(_done) : "r"(_mbar), "r"(_parity) : "memory"); \
    if (!_done) { \
        asm volatile( \
            "{\n\t" \
            ".reg .pred P1;\n\t" \
            "WAIT_LOOP_%=:\n\t" \
            "mbarrier.try_wait.parity.relaxed.cta.shared::cta.b64 P1, [%0], %1, 0x989680;\n\t" \
            "@P1 bra.uni WAIT_DONE_%=;\n\t" \
            "bra.uni WAIT_LOOP_%=;\n\t" \
            "WAIT_DONE_%=:\n\t" \
            "}" \
            :: "r"(_mbar), "r"(_parity) : "memory"); \
    } \
} while (0)

__device__ __forceinline__ void ldsm_x4(uint32_t& r0, uint32_t& r1,
                                        uint32_t& r2, uint32_t& r3, uint32_t addr) {
    asm volatile("ldmatrix.sync.aligned.m8n8.x4.shared.b16 {%0,%1,%2,%3}, [%4];"
                 : "=r"(r0), "=r"(r1), "=r"(r2), "=r"(r3) : "r"(addr));
}

__device__ __forceinline__ void mma16816(float* c, const uint32_t* a, const uint32_t* b) {
    asm volatile(
        "mma.sync.aligned.m16n8k16.row.col.f32.f16.f16.f32 "
        "{%0,%1,%2,%3}, {%4,%5,%6,%7}, {%8,%9}, {%0,%1,%2,%3};"
        : "+f"(c[0]), "+f"(c[1]), "+f"(c[2]), "+f"(c[3])
        : "r"(a[0]), "r"(a[1]), "r"(a[2]), "r"(a[3]), "r"(b[0]), "r"(b[1]));
}

// ============================================================================
// GEMM: out[M,N] = A[M,K] * B[N,K]^T * scale[n] + bias[n]
//   R13 pipeline + split consumer wait: probe next stage's full-barrier
//   between ks2 and ks3, consume the predicate after ks3's MMAs.
// ============================================================================
__global__ void __launch_bounds__(THREADS, 2) gemm_kernel(
    const float* __restrict__ scales,
    const float* __restrict__ bias,
    float* __restrict__ out)
{
    extern __shared__ char smem[];
    const uint32_t sb = smem_u32(smem);
    const int tid = threadIdx.x;
    const int lane = tid & 31;
    const int wid = tid >> 5;
    const int wm = wid >> 2;       // 0..1
    const int wn = wid & 3;        // 0..3

    // CTA swizzle for L2 reuse
    constexpr int TILES_N = D_OUT / N_TILE;   // 32
    constexpr int GROUP = 8;
    const int bid = blockIdx.x;
    const int r = bid % (GROUP * TILES_N);
    const int tile_m = (bid / (GROUP * TILES_N)) * GROUP + (r % GROUP);
    const int tile_n = r / GROUP;
    const int row0 = tile_m * M_TILE;
    const int col0 = tile_n * N_TILE;

    // ---- barrier init ----
    if (tid == 0) {
        #pragma unroll
        for (int s = 0; s < STAGES; s++) {
            MBARRIER_INIT(sb + SMEM_BARS + s * 16, THREADS);  // full: 256 cp arrivals
            MBARRIER_INIT(sb + SMEM_BARS + s * 16 + 8, 8);    // empty: 8 warp arrivals
        }
    }
    __syncthreads();

    // ---- precomputed producer addressing ----
    const int trow = tid >> 3;
    const int tc16 = tid & 7;
    const __half* pA = g_A + (size_t)(row0 + trow) * D_IN + tc16 * 8;
    const __half* pB = g_B + (size_t)(col0 + trow) * D_IN + tc16 * 8;
    const uint32_t doff = (uint32_t)(trow * 128) +
                          (((uint32_t)tc16 * 16) ^ (((uint32_t)(trow & 7)) << 4));

    auto issue_A = [&](const __half* srcA, int stage) {
        const uint32_t dA = sb + SMEM_TILES + stage * STAGE_BYTES + doff;
        #pragma unroll
        for (int j = 0; j < 4; j++)
            cp_async16(dA + j * 4096, srcA + (size_t)j * 32 * D_IN);
    };
    auto issue_B = [&](const __half* srcB, int stage) {
        const uint32_t dB = sb + SMEM_TILES + stage * STAGE_BYTES + A_BYTES + doff;
        #pragma unroll
        for (int j = 0; j < 4; j++)
            cp_async16(dB + j * 4096, srcB + (size_t)j * 32 * D_IN);
    };

    // ---- prologue: fill stages 0,1; arrive on full when done ----
    #pragma unroll
    for (int s = 0; s < STAGES - 1; s++) {
        issue_A(pA + s * K_TILE, s);
        issue_B(pB + s * K_TILE, s);
        CP_ASYNC_MBAR_ARRIVE_NOINC(sb + SMEM_BARS + s * 16);
    }

    // ---- per-thread ldmatrix base addresses (verified layout) ----
    const uint32_t xm    = (lane & 7) << 4;
    const uint32_t xm_hi = xm & 0x60;
    const uint32_t xm_lo = xm & 0x10;

    uint32_t aBase[4];
    {
        uint32_t colp = ((uint32_t)(lane >> 4) << 4) ^ xm_lo;
        #pragma unroll
        for (int m = 0; m < 4; m++)
            aBase[m] = (uint32_t)((wm * 64 + m * 16 + (lane & 15)) * 128) + colp;
    }
    uint32_t bBase[2];
    {
        uint32_t colp = (((uint32_t)(lane >> 3) & 1) << 4) ^ xm_lo;
        uint32_t rowB = (uint32_t)(wn * 32 + ((lane >> 4) << 3) + (lane & 7));
        #pragma unroll
        for (int ch = 0; ch < 2; ch++)
            bBase[ch] = (rowB + ch * 16) * 128 + colp;
    }

    float acc[4][4][4];
    #pragma unroll
    for (int m = 0; m < 4; m++)
        #pragma unroll
        for (int n = 0; n < 4; n++)
            #pragma unroll
            for (int v = 0; v < 4; v++) acc[m][n][v] = 0.0f;

    // ---- main loop: per-warp pipeline, unrolled by STAGES ----
    const __half* srcA = pA + (STAGES - 1) * K_TILE;
    const __half* srcB = pB + (STAGES - 1) * K_TILE;
    int ps = STAGES - 1, pp = 1;   // producer cursor
    int fs = 0, fp = 0;            // consumer cursor

    // prologue wait: stage 0 ready
    MBARRIER_WAIT_PARITY(sb + SMEM_BARS, 0);

    #pragma unroll 3
    for (int kc = 0; kc < NUM_K; kc++) {
        // stage fs data is ready (waited at end of previous iteration)
        const uint32_t sA  = sb + SMEM_TILES + fs * STAGE_BYTES;
        const uint32_t sBb = sA + A_BYTES;

        auto do_loads = [&](int ks, uint32_t (&a)[4][4], uint32_t (&b)[4][2]) {
            const uint32_t kofs = ((uint32_t)(ks * 32)) ^ xm_hi;
            #pragma unroll
            for (int m = 0; m < 4; m++)
                ldsm_x4(a[m][0], a[m][1], a[m][2], a[m][3], sA + aBase[m] + kofs);
            #pragma unroll
            for (int ch = 0; ch < 2; ch++) {
                uint32_t r0, r1, r2, r3;
                ldsm_x4(r0, r1, r2, r3, sBb + bBase[ch] + kofs);
                b[ch * 2 + 0][0] = r0; b[ch * 2 + 0][1] = r1;
                b[ch * 2 + 1][0] = r2; b[ch * 2 + 1][1] = r3;
            }
        };
        auto do_mma = [&](uint32_t (&a)[4][4], uint32_t (&b)[4][2]) {
            #pragma unroll
            for (int m = 0; m < 4; m++)
                #pragma unroll
                for (int n = 0; n < 4; n++)
                    mma16816(acc[m][n], a[m], b[n]);
        };

        const bool refill = (kc + STAGES - 1 < NUM_K);
        const bool have_next = (kc + 1 < NUM_K);
        uint32_t a[4][4];
        uint32_t b[4][2];

        // ks=0: stage-start LSU window serves only LDSMs
        do_loads(0, a, b); do_mma(a, b);

        // producer half 1: A tile of chunk kc+2
        if (refill) {
            MBARRIER_WAIT_PARITY_RELAXED(sb + SMEM_BARS + ps * 16 + 8, pp);
            issue_A(srcA, ps);
        }

        do_loads(1, a, b); do_mma(a, b);

        // producer half 2: B tile + completion arrive (covers both halves)
        if (refill) {
            issue_B(srcB, ps);
            CP_ASYNC_MBAR_ARRIVE_NOINC(sb + SMEM_BARS + ps * 16);
            srcA += K_TILE;
            srcB += K_TILE;
        }
        if (++ps == STAGES) { ps = 0; pp ^= 1; }

        do_loads(2, a, b); do_mma(a, b);

        // next consumer slot + EARLY PROBE of its full-barrier: the ~90cyc
        // try_wait result latency overlaps ks3's loads + MMAs below.
        const int nfs = (fs + 1 == STAGES) ? 0 : fs + 1;
        const int nfp = (fs + 1 == STAGES) ? (fp ^ 1) : fp;
        uint32_t next_ready = 1;
        if (have_next)
            MBARRIER_TRY_ONCE(next_ready, sb + SMEM_BARS + nfs * 16, nfp);

        // ks=3: loads, early stage release (smem reads done), then MMAs
        do_loads(3, a, b);
        if (lane == 0)
            MBARRIER_ARRIVE(sb + SMEM_BARS + fs * 16 + 8);
        do_mma(a, b);

        // consume the probe; spin only if the producer hasn't finished
        if (have_next && !next_ready)
            MBARRIER_SPIN(sb + SMEM_BARS + nfs * 16, nfp);

        fs = nfs; fp = nfp;
    }

    // ---- epilogue: acc * scale[col] + bias[col] ----
    const int cbase = col0 + wn * 32 + (lane & 3) * 2;
    float2 sc[4], bi[4];
    #pragma unroll
    for (int n = 0; n < 4; n++) {
        sc[n] = __ldg(reinterpret_cast<const float2*>(scales + cbase + n * 8));
        bi[n] = __ldg(reinterpret_cast<const float2*>(bias   + cbase + n * 8));
    }
    const int rbase = row0 + wm * 64 + (lane >> 2);
    #pragma unroll
    for (int m = 0; m < 4; m++) {
        #pragma unroll
        for (int n = 0; n < 4; n++) {
            const size_t o0 = (size_t)(rbase + m * 16) * D_OUT + cbase + n * 8;
            const size_t o1 = o0 + 8 * D_OUT;
            float2 v0, v1;
            v0.x = fmaf(acc[m][n][0], sc[n].x, bi[n].x);
            v0.y = fmaf(acc[m][n][1], sc[n].y, bi[n].y);
            v1.x = fmaf(acc[m][n][2], sc[n].x, bi[n].x);
            v1.y = fmaf(acc[m][n][3], sc[n].y, bi[n].y);
            *reinterpret_cast<float2*>(out + o0) = v0;
            *reinterpret_cast<float2*>(out + o1) = v1;
        }
    }
}

// ============================================================================
// Host
// ============================================================================
extern "C" void kernel_launch(void* const* d_in, const int* in_sizes, int n_in,
                              void* d_out, int out_size)
{
    const float* x  = (const float*)d_in[0];
    const int*   wq = (const int*)  d_in[1];
    const float* sc = (const float*)d_in[2];
    const float* bi = (const float*)d_in[3];
    float* out = (float*)d_out;

    prep_kernel<<<6144, 256>>>(x, wq);

    cudaFuncSetAttribute(gemm_kernel, cudaFuncAttributeMaxDynamicSharedMemorySize,
                         SMEM_TOTAL);

    const int grid = (TOKENS / M_TILE) * (D_OUT / N_TILE);  // 2048
    gemm_kernel<<<grid, THREADS, SMEM_TOTAL>>>(sc, bi, out);
}

// round 15
// speedup vs baseline: 1.0031x; 1.0031x over previous
#include <cuda_runtime.h>
#include <cuda_fp16.h>
#include <cstdint>

// ============================================================================
// Problem sizes
// ============================================================================
#define TOKENS 8192
#define D_IN   4096
#define D_OUT  4096

// Scratch (device globals; no allocations allowed)
__device__ __half g_A[(size_t)TOKENS * D_IN];   // 64 MB: x in fp16
__device__ __half g_B[(size_t)D_OUT  * D_IN];   // 32 MB: W in fp16 (exact)

// ============================================================================
// GEMM configuration: CTA 128x128x64, 256 threads, 2 CTAs/SM
// ============================================================================
constexpr int M_TILE = 128;
constexpr int N_TILE = 128;
constexpr int K_TILE = 64;                 // 64 fp16 = 128 B rows
constexpr int STAGES = 3;
constexpr int NUM_K  = D_IN / K_TILE;      // 64
constexpr int THREADS = 256;               // 8 warps: 2(m) x 4(n), warp tile 64x32

constexpr int A_BYTES = M_TILE * 128;      // 16 KB
constexpr int B_BYTES = N_TILE * 128;      // 16 KB
constexpr int STAGE_BYTES = A_BYTES + B_BYTES;     // 32 KB
constexpr int SMEM_BARS  = 0;              // full[s]=s*16, empty[s]=s*16+8
constexpr int SMEM_TILES = 1024;
constexpr int SMEM_TOTAL = SMEM_TILES + STAGES * STAGE_BYTES;  // 99328 -> 2 CTAs/SM

// ============================================================================
// Prep kernel: MLP=4 (64 B/iter, loads front-batched) + streaming stores.
// x/wq are read exactly once and A/B consumed much later -> .cs both ways.
// ============================================================================
constexpr size_t W_QUADS = (size_t)D_OUT * D_IN / 16;   // 4x int4 per iter
constexpr size_t X_QUADS = (size_t)TOKENS * D_IN / 16;  // 4x float4 per iter

__global__ void prep_kernel(const float* __restrict__ x, const int* __restrict__ wq) {
    const size_t nth = (size_t)gridDim.x * blockDim.x;
    const size_t t0 = (size_t)blockIdx.x * blockDim.x + threadIdx.x;

    for (size_t i = t0; i < W_QUADS; i += nth) {
        const int4* src = reinterpret_cast<const int4*>(wq) + i * 4;
        int4 v0 = __ldcs(src + 0);
        int4 v1 = __ldcs(src + 1);
        int4 v2 = __ldcs(src + 2);
        int4 v3 = __ldcs(src + 3);
        uint4 p0, p1;
        {
            __half2 a0 = __floats2half2_rn((float)v0.x, (float)v0.y);  // int8 exact
            __half2 a1 = __floats2half2_rn((float)v0.z, (float)v0.w);
            __half2 a2 = __floats2half2_rn((float)v1.x, (float)v1.y);
            __half2 a3 = __floats2half2_rn((float)v1.z, (float)v1.w);
            p0.x = *reinterpret_cast<uint32_t*>(&a0);
            p0.y = *reinterpret_cast<uint32_t*>(&a1);
            p0.z = *reinterpret_cast<uint32_t*>(&a2);
            p0.w = *reinterpret_cast<uint32_t*>(&a3);
        }
        {
            __half2 a0 = __floats2half2_rn((float)v2.x, (float)v2.y);
            __half2 a1 = __floats2half2_rn((float)v2.z, (float)v2.w);
            __half2 a2 = __floats2half2_rn((float)v3.x, (float)v3.y);
            __half2 a3 = __floats2half2_rn((float)v3.z, (float)v3.w);
            p1.x = *reinterpret_cast<uint32_t*>(&a0);
            p1.y = *reinterpret_cast<uint32_t*>(&a1);
            p1.z = *reinterpret_cast<uint32_t*>(&a2);
            p1.w = *reinterpret_cast<uint32_t*>(&a3);
        }
        __stcs(reinterpret_cast<uint4*>(&g_B[i * 16]), p0);
        __stcs(reinterpret_cast<uint4*>(&g_B[i * 16 + 8]), p1);
    }

    for (size_t j = t0; j < X_QUADS; j += nth) {
        const float4* src = reinterpret_cast<const float4*>(x) + j * 4;
        float4 v0 = __ldcs(src + 0);
        float4 v1 = __ldcs(src + 1);
        float4 v2 = __ldcs(src + 2);
        float4 v3 = __ldcs(src + 3);
        uint4 p0, p1;
        {
            __half2 a0 = __floats2half2_rn(v0.x, v0.y);
            __half2 a1 = __floats2half2_rn(v0.z, v0.w);
            __half2 a2 = __floats2half2_rn(v1.x, v1.y);
            __half2 a3 = __floats2half2_rn(v1.z, v1.w);
            p0.x = *reinterpret_cast<uint32_t*>(&a0);
            p0.y = *reinterpret_cast<uint32_t*>(&a1);
            p0.z = *reinterpret_cast<uint32_t*>(&a2);
            p0.w = *reinterpret_cast<uint32_t*>(&a3);
        }
        {
            __half2 a0 = __floats2half2_rn(v2.x, v2.y);
            __half2 a1 = __floats2half2_rn(v2.z, v2.w);
            __half2 a2 = __floats2half2_rn(v3.x, v3.y);
            __half2 a3 = __floats2half2_rn(v3.z, v3.w);
            p1.x = *reinterpret_cast<uint32_t*>(&a0);
            p1.y = *reinterpret_cast<uint32_t*>(&a1);
            p1.z = *reinterpret_cast<uint32_t*>(&a2);
            p1.w = *reinterpret_cast<uint32_t*>(&a3);
        }
        __stcs(reinterpret_cast<uint4*>(&g_A[j * 16]), p0);
        __stcs(reinterpret_cast<uint4*>(&g_A[j * 16 + 8]), p1);
    }
}

// ============================================================================
// PTX helpers
// ============================================================================
__device__ __forceinline__ uint32_t smem_u32(const void* p) {
    uint32_t a;
    asm("{ .reg .u64 t; cvta.to.shared.u64 t, %1; cvt.u32.u64 %0, t; }"
        : "=r"(a) : "l"(p));
    return a;
}

__device__ __forceinline__ void cp_async16(uint32_t dst, const void* src) {
    asm volatile("cp.async.cg.shared.global [%0], [%1], 16;"
                 :: "r"(dst), "l"(src) : "memory");
}

#define MBARRIER_INIT(addr, cnt) \
    asm volatile("mbarrier.init.shared.b64 [%0], %1;" \
                 :: "r"((uint32_t)(addr)), "r"((uint32_t)(cnt)) : "memory")

#define MBARRIER_ARRIVE(addr) \
    asm volatile("mbarrier.arrive.shared.b64 _, [%0];" \
                 :: "r"((uint32_t)(addr)) : "memory")

// Each thread's outstanding cp.asyncs arrive (count 1) on the mbarrier when
// they ALL complete; .noinc counts against the barrier's init count.
#define CP_ASYNC_MBAR_ARRIVE_NOINC(addr) \
    asm volatile("cp.async.mbarrier.arrive.noinc.shared.b64 [%0];" \
                 :: "r"((uint32_t)(addr)) : "memory")

#define MBARRIER_WAIT_PARITY(mbar_smem_addr, phase_parity) do { \
    uint32_t _mbar = (uint32_t)(mbar_smem_addr); \
    uint32_t _parity = (uint32_t)(phase_parity); \
    uint32_t _done; \
    asm volatile( \
        "{\n\t" \
        ".reg .pred p;\n\t" \
        "mbarrier.try_wait.parity.acquire.cta.shared::cta.b64 p, [%1], %2;\n\t" \
        "selp.b32 %0, 1, 0, p;\n\t" \
        "}" \
        : "=r"(_done) : "r"(_mbar), "r"(_parity) : "memory"); \
    if (!_done) { \
        asm volatile( \
            "{\n\t" \
            ".reg .pred P1;\n\t" \
            "WAIT_LOOP_%=:\n\t" \
            "mbarrier.try_wait.parity.acquire.cta.shared::cta.b64 P1, [%0], %1, 0x989680;\n\t" \
            "@P1 bra.uni WAIT_DONE_%=;\n\t" \
            "bra.uni WAIT_LOOP_%=;\n\t" \
            "WAIT_DONE_%=:\n\t" \
            "}" \
            :: "r"(_mbar), "r"(_parity) : "memory"); \
    } \
} while (0)

// Relaxed wait: safe ONLY when all post-wait accesses are async-proxy
// (cp.async issues) — the producer path here.
#define MBARRIER_WAIT_PARITY_RELAXED(mbar_smem_addr, phase_parity) do { \
    uint32_t _mbar = (uint32_t)(mbar_smem_addr); \
    uint32_t _parity = (uint32_t)(phase_parity); \
    uint32_t _done; \
    asm volatile( \
        "{\n\t" \
        ".reg .pred p;\n\t" \
        "mbarrier.try_wait.parity.relaxed.cta.shared::cta.b64 p, [%1], %2;\n\t" \
        "selp.b32 %0, 1, 0, p;\n\t" \
        "}" \
        : "=r"(_done) : "r"(_mbar), "r"(_parity) : "memory"); \
    if (!_done) { \
        asm volatile( \
            "{\n\t" \
            ".reg .pred P1;\n\t" \
            "WAIT_LOOP_%=:\n\t" \
            "mbarrier.try_wait.parity.relaxed.cta.shared::cta.b64 P1, [%0], %1, 0x989680;\n\t" \
            "@P1 bra.uni WAIT_DONE_%=;\n\t" \
            "bra.uni WAIT_LOOP_%=;\n\t" \
            "WAIT_DONE_%=:\n\t" \
            "}" \
            :: "r"(_mbar), "r"(_parity) : "memory"); \
    } \
} while (0)

__device__ __forceinline__ void ldsm_x4(uint32_t& r0, uint32_t& r1,
                                        uint32_t& r2, uint32_t& r3, uint32_t addr) {
    asm volatile("ldmatrix.sync.aligned.m8n8.x4.shared.b16 {%0,%1,%2,%3}, [%4];"
                 : "=r"(r0), "=r"(r1), "=r"(r2), "=r"(r3) : "r"(addr));
}

__device__ __forceinline__ void mma16816(float* c, const uint32_t* a, const uint32_t* b) {
    asm volatile(
        "mma.sync.aligned.m16n8k16.row.col.f32.f16.f16.f32 "
        "{%0,%1,%2,%3}, {%4,%5,%6,%7}, {%8,%9}, {%0,%1,%2,%3};"
        : "+f"(c[0]), "+f"(c[1]), "+f"(c[2]), "+f"(c[3])
        : "r"(a[0]), "r"(a[1]), "r"(a[2]), "r"(a[3]), "r"(b[0]), "r"(b[1]));
}

// ============================================================================
// GEMM: out[M,N] = A[M,K] * B[N,K]^T * scale[n] + bias[n]
//   R13 champion pipeline, unchanged: per-warp mbarrier pipeline, A-half
//   after ks0, B-half + arrive after ks1, early release after ks3 LDSMs.
// ============================================================================
__global__ void __launch_bounds__(THREADS, 2) gemm_kernel(
    const float* __restrict__ scales,
    const float* __restrict__ bias,
    float* __restrict__ out)
{
    extern __shared__ char smem[];
    const uint32_t sb = smem_u32(smem);
    const int tid = threadIdx.x;
    const int lane = tid & 31;
    const int wid = tid >> 5;
    const int wm = wid >> 2;       // 0..1
    const int wn = wid & 3;        // 0..3

    // CTA swizzle for L2 reuse
    constexpr int TILES_N = D_OUT / N_TILE;   // 32
    constexpr int GROUP = 8;
    const int bid = blockIdx.x;
    const int r = bid % (GROUP * TILES_N);
    const int tile_m = (bid / (GROUP * TILES_N)) * GROUP + (r % GROUP);
    const int tile_n = r / GROUP;
    const int row0 = tile_m * M_TILE;
    const int col0 = tile_n * N_TILE;

    // ---- barrier init ----
    if (tid == 0) {
        #pragma unroll
        for (int s = 0; s < STAGES; s++) {
            MBARRIER_INIT(sb + SMEM_BARS + s * 16, THREADS);  // full: 256 cp arrivals
            MBARRIER_INIT(sb + SMEM_BARS + s * 16 + 8, 8);    // empty: 8 warp arrivals
        }
    }
    __syncthreads();

    // ---- precomputed producer addressing ----
    const int trow = tid >> 3;
    const int tc16 = tid & 7;
    const __half* pA = g_A + (size_t)(row0 + trow) * D_IN + tc16 * 8;
    const __half* pB = g_B + (size_t)(col0 + trow) * D_IN + tc16 * 8;
    const uint32_t doff = (uint32_t)(trow * 128) +
                          (((uint32_t)tc16 * 16) ^ (((uint32_t)(trow & 7)) << 4));

    auto issue_A = [&](const __half* srcA, int stage) {
        const uint32_t dA = sb + SMEM_TILES + stage * STAGE_BYTES + doff;
        #pragma unroll
        for (int j = 0; j < 4; j++)
            cp_async16(dA + j * 4096, srcA + (size_t)j * 32 * D_IN);
    };
    auto issue_B = [&](const __half* srcB, int stage) {
        const uint32_t dB = sb + SMEM_TILES + stage * STAGE_BYTES + A_BYTES + doff;
        #pragma unroll
        for (int j = 0; j < 4; j++)
            cp_async16(dB + j * 4096, srcB + (size_t)j * 32 * D_IN);
    };

    // ---- prologue: fill stages 0,1; arrive on full when done ----
    #pragma unroll
    for (int s = 0; s < STAGES - 1; s++) {
        issue_A(pA + s * K_TILE, s);
        issue_B(pB + s * K_TILE, s);
        CP_ASYNC_MBAR_ARRIVE_NOINC(sb + SMEM_BARS + s * 16);
    }

    // ---- per-thread ldmatrix base addresses (verified layout) ----
    const uint32_t xm    = (lane & 7) << 4;
    const uint32_t xm_hi = xm & 0x60;
    const uint32_t xm_lo = xm & 0x10;

    uint32_t aBase[4];
    {
        uint32_t colp = ((uint32_t)(lane >> 4) << 4) ^ xm_lo;
        #pragma unroll
        for (int m = 0; m < 4; m++)
            aBase[m] = (uint32_t)((wm * 64 + m * 16 + (lane & 15)) * 128) + colp;
    }
    uint32_t bBase[2];
    {
        uint32_t colp = (((uint32_t)(lane >> 3) & 1) << 4) ^ xm_lo;
        uint32_t rowB = (uint32_t)(wn * 32 + ((lane >> 4) << 3) + (lane & 7));
        #pragma unroll
        for (int ch = 0; ch < 2; ch++)
            bBase[ch] = (rowB + ch * 16) * 128 + colp;
    }

    float acc[4][4][4];
    #pragma unroll
    for (int m = 0; m < 4; m++)
        #pragma unroll
        for (int n = 0; n < 4; n++)
            #pragma unroll
            for (int v = 0; v < 4; v++) acc[m][n][v] = 0.0f;

    // ---- main loop: per-warp pipeline, unrolled by STAGES ----
    const __half* srcA = pA + (STAGES - 1) * K_TILE;
    const __half* srcB = pB + (STAGES - 1) * K_TILE;
    int ps = STAGES - 1, pp = 1;   // producer cursor
    int fs = 0, fp = 0;            // consumer cursor
    #pragma unroll 3
    for (int kc = 0; kc < NUM_K; kc++) {
        // consumer: wait until all 256 threads' loads for this stage landed
        MBARRIER_WAIT_PARITY(sb + SMEM_BARS + fs * 16, fp);

        const uint32_t sA  = sb + SMEM_TILES + fs * STAGE_BYTES;
        const uint32_t sBb = sA + A_BYTES;

        auto do_loads = [&](int ks, uint32_t (&a)[4][4], uint32_t (&b)[4][2]) {
            const uint32_t kofs = ((uint32_t)(ks * 32)) ^ xm_hi;
            #pragma unroll
            for (int m = 0; m < 4; m++)
                ldsm_x4(a[m][0], a[m][1], a[m][2], a[m][3], sA + aBase[m] + kofs);
            #pragma unroll
            for (int ch = 0; ch < 2; ch++) {
                uint32_t r0, r1, r2, r3;
                ldsm_x4(r0, r1, r2, r3, sBb + bBase[ch] + kofs);
                b[ch * 2 + 0][0] = r0; b[ch * 2 + 0][1] = r1;
                b[ch * 2 + 1][0] = r2; b[ch * 2 + 1][1] = r3;
            }
        };
        auto do_mma = [&](uint32_t (&a)[4][4], uint32_t (&b)[4][2]) {
            #pragma unroll
            for (int m = 0; m < 4; m++)
                #pragma unroll
                for (int n = 0; n < 4; n++)
                    mma16816(acc[m][n], a[m], b[n]);
        };

        const bool refill = (kc + STAGES - 1 < NUM_K);
        uint32_t a[4][4];
        uint32_t b[4][2];

        // ks=0: stage-start LSU window serves only LDSMs
        do_loads(0, a, b); do_mma(a, b);

        // producer half 1: A tile of chunk kc+2
        if (refill) {
            MBARRIER_WAIT_PARITY_RELAXED(sb + SMEM_BARS + ps * 16 + 8, pp);
            issue_A(srcA, ps);
        }

        do_loads(1, a, b); do_mma(a, b);

        // producer half 2: B tile + completion arrive (covers both halves)
        if (refill) {
            issue_B(srcB, ps);
            CP_ASYNC_MBAR_ARRIVE_NOINC(sb + SMEM_BARS + ps * 16);
            srcA += K_TILE;
            srcB += K_TILE;
        }
        if (++ps == STAGES) { ps = 0; pp ^= 1; }

        do_loads(2, a, b); do_mma(a, b);

        // ks=3: loads, EARLY stage release (smem reads done), then MMAs
        do_loads(3, a, b);
        if (lane == 0)
            MBARRIER_ARRIVE(sb + SMEM_BARS + fs * 16 + 8);
        do_mma(a, b);

        if (++fs == STAGES) { fs = 0; fp ^= 1; }
    }

    // ---- epilogue: acc * scale[col] + bias[col] ----
    const int cbase = col0 + wn * 32 + (lane & 3) * 2;
    float2 sc[4], bi[4];
    #pragma unroll
    for (int n = 0; n < 4; n++) {
        sc[n] = __ldg(reinterpret_cast<const float2*>(scales + cbase + n * 8));
        bi[n] = __ldg(reinterpret_cast<const float2*>(bias   + cbase + n * 8));
    }
    const int rbase = row0 + wm * 64 + (lane >> 2);
    #pragma unroll
    for (int m = 0; m < 4; m++) {
        #pragma unroll
        for (int n = 0; n < 4; n++) {
            const size_t o0 = (size_t)(rbase + m * 16) * D_OUT + cbase + n * 8;
            const size_t o1 = o0 + 8 * D_OUT;
            float2 v0, v1;
            v0.x = fmaf(acc[m][n][0], sc[n].x, bi[n].x);
            v0.y = fmaf(acc[m][n][1], sc[n].y, bi[n].y);
            v1.x = fmaf(acc[m][n][2], sc[n].x, bi[n].x);
            v1.y = fmaf(acc[m][n][3], sc[n].y, bi[n].y);
            *reinterpret_cast<float2*>(out + o0) = v0;
            *reinterpret_cast<float2*>(out + o1) = v1;
        }
    }
}

// ============================================================================
// Host
// ============================================================================
extern "C" void kernel_launch(void* const* d_in, const int* in_sizes, int n_in,
                              void* d_out, int out_size)
{
    const float* x  = (const float*)d_in[0];
    const int*   wq = (const int*)  d_in[1];
    const float* sc = (const float*)d_in[2];
    const float* bi = (const float*)d_in[3];
    float* out = (float*)d_out;

    prep_kernel<<<4096, 256>>>(x, wq);

    cudaFuncSetAttribute(gemm_kernel, cudaFuncAttributeMaxDynamicSharedMemorySize,
                         SMEM_TOTAL);

    const int grid = (TOKENS / M_TILE) * (D_OUT / N_TILE);  // 2048
    gemm_kernel<<<grid, THREADS, SMEM_TOTAL>>>(sc, bi, out);
}

// round 16
// speedup vs baseline: 1.0032x; 1.0001x over previous
#include <cuda_runtime.h>
#include <cuda_fp16.h>
#include <cstdint>

// ============================================================================
// Problem sizes
// ============================================================================
#define TOKENS 8192
#define D_IN   4096
#define D_OUT  4096

// Scratch (device globals; no allocations allowed)
__device__ __half g_A[(size_t)TOKENS * D_IN];   // 64 MB: x in fp16
__device__ __half g_B[(size_t)D_OUT  * D_IN];   // 32 MB: W in fp16 (exact)

// ============================================================================
// GEMM configuration: CTA 128x128x64, 256 threads, 2 CTAs/SM
// ============================================================================
constexpr int M_TILE = 128;
constexpr int N_TILE = 128;
constexpr int K_TILE = 64;                 // 64 fp16 = 128 B rows
constexpr int STAGES = 3;
constexpr int NUM_K  = D_IN / K_TILE;      // 64
constexpr int THREADS = 256;               // 8 warps: 2(m) x 4(n), warp tile 64x32

constexpr int A_BYTES = M_TILE * 128;      // 16 KB
constexpr int B_BYTES = N_TILE * 128;      // 16 KB
constexpr int STAGE_BYTES = A_BYTES + B_BYTES;     // 32 KB
constexpr int SMEM_BARS  = 0;              // full[s]=s*16, empty[s]=s*16+8
constexpr int SMEM_TILES = 1024;
constexpr int SMEM_TOTAL = SMEM_TILES + STAGES * STAGE_BYTES;  // 99328 -> 2 CTAs/SM

// ============================================================================
// Prep kernel: MLP=4 (64 B/iter, loads front-batched) + streaming stores.
// ============================================================================
constexpr size_t W_QUADS = (size_t)D_OUT * D_IN / 16;   // 4x int4 per iter
constexpr size_t X_QUADS = (size_t)TOKENS * D_IN / 16;  // 4x float4 per iter

__global__ void prep_kernel(const float* __restrict__ x, const int* __restrict__ wq) {
    const size_t nth = (size_t)gridDim.x * blockDim.x;
    const size_t t0 = (size_t)blockIdx.x * blockDim.x + threadIdx.x;

    for (size_t i = t0; i < W_QUADS; i += nth) {
        const int4* src = reinterpret_cast<const int4*>(wq) + i * 4;
        int4 v0 = __ldcs(src + 0);
        int4 v1 = __ldcs(src + 1);
        int4 v2 = __ldcs(src + 2);
        int4 v3 = __ldcs(src + 3);
        uint4 p0, p1;
        {
            __half2 a0 = __floats2half2_rn((float)v0.x, (float)v0.y);  // int8 exact
            __half2 a1 = __floats2half2_rn((float)v0.z, (float)v0.w);
            __half2 a2 = __floats2half2_rn((float)v1.x, (float)v1.y);
            __half2 a3 = __floats2half2_rn((float)v1.z, (float)v1.w);
            p0.x = *reinterpret_cast<uint32_t*>(&a0);
            p0.y = *reinterpret_cast<uint32_t*>(&a1);
            p0.z = *reinterpret_cast<uint32_t*>(&a2);
            p0.w = *reinterpret_cast<uint32_t*>(&a3);
        }
        {
            __half2 a0 = __floats2half2_rn((float)v2.x, (float)v2.y);
            __half2 a1 = __floats2half2_rn((float)v2.z, (float)v2.w);
            __half2 a2 = __floats2half2_rn((float)v3.x, (float)v3.y);
            __half2 a3 = __floats2half2_rn((float)v3.z, (float)v3.w);
            p1.x = *reinterpret_cast<uint32_t*>(&a0);
            p1.y = *reinterpret_cast<uint32_t*>(&a1);
            p1.z = *reinterpret_cast<uint32_t*>(&a2);
            p1.w = *reinterpret_cast<uint32_t*>(&a3);
        }
        __stcs(reinterpret_cast<uint4*>(&g_B[i * 16]), p0);
        __stcs(reinterpret_cast<uint4*>(&g_B[i * 16 + 8]), p1);
    }

    for (size_t j = t0; j < X_QUADS; j += nth) {
        const float4* src = reinterpret_cast<const float4*>(x) + j * 4;
        float4 v0 = __ldcs(src + 0);
        float4 v1 = __ldcs(src + 1);
        float4 v2 = __ldcs(src + 2);
        float4 v3 = __ldcs(src + 3);
        uint4 p0, p1;
        {
            __half2 a0 = __floats2half2_rn(v0.x, v0.y);
            __half2 a1 = __floats2half2_rn(v0.z, v0.w);
            __half2 a2 = __floats2half2_rn(v1.x, v1.y);
            __half2 a3 = __floats2half2_rn(v1.z, v1.w);
            p0.x = *reinterpret_cast<uint32_t*>(&a0);
            p0.y = *reinterpret_cast<uint32_t*>(&a1);
            p0.z = *reinterpret_cast<uint32_t*>(&a2);
            p0.w = *reinterpret_cast<uint32_t*>(&a3);
        }
        {
            __half2 a0 = __floats2half2_rn(v2.x, v2.y);
            __half2 a1 = __floats2half2_rn(v2.z, v2.w);
            __half2 a2 = __floats2half2_rn(v3.x, v3.y);
            __half2 a3 = __floats2half2_rn(v3.z, v3.w);
            p1.x = *reinterpret_cast<uint32_t*>(&a0);
            p1.y = *reinterpret_cast<uint32_t*>(&a1);
            p1.z = *reinterpret_cast<uint32_t*>(&a2);
            p1.w = *reinterpret_cast<uint32_t*>(&a3);
        }
        __stcs(reinterpret_cast<uint4*>(&g_A[j * 16]), p0);
        __stcs(reinterpret_cast<uint4*>(&g_A[j * 16 + 8]), p1);
    }
}

// ============================================================================
// PTX helpers
// ============================================================================
__device__ __forceinline__ uint32_t smem_u32(const void* p) {
    uint32_t a;
    asm("{ .reg .u64 t; cvta.to.shared.u64 t, %1; cvt.u32.u64 %0, t; }"
        : "=r"(a) : "l"(p));
    return a;
}

__device__ __forceinline__ void cp_async16(uint32_t dst, const void* src) {
    asm volatile("cp.async.cg.shared.global [%0], [%1], 16;"
                 :: "r"(dst), "l"(src) : "memory");
}

#define MBARRIER_INIT(addr, cnt) \
    asm volatile("mbarrier.init.shared.b64 [%0], %1;" \
                 :: "r"((uint32_t)(addr)), "r"((uint32_t)(cnt)) : "memory")

#define MBARRIER_ARRIVE(addr) \
    asm volatile("mbarrier.arrive.shared.b64 _, [%0];" \
                 :: "r"((uint32_t)(addr)) : "memory")

// Each thread's outstanding cp.asyncs arrive (count 1) on the mbarrier when
// they ALL complete; .noinc counts against the barrier's init count.
#define CP_ASYNC_MBAR_ARRIVE_NOINC(addr) \
    asm volatile("cp.async.mbarrier.arrive.noinc.shared.b64 [%0];" \
                 :: "r"((uint32_t)(addr)) : "memory")

#define MBARRIER_WAIT_PARITY(mbar_smem_addr, phase_parity) do { \
    uint32_t _mbar = (uint32_t)(mbar_smem_addr); \
    uint32_t _parity = (uint32_t)(phase_parity); \
    uint32_t _done; \
    asm volatile( \
        "{\n\t" \
        ".reg .pred p;\n\t" \
        "mbarrier.try_wait.parity.acquire.cta.shared::cta.b64 p, [%1], %2;\n\t" \
        "selp.b32 %0, 1, 0, p;\n\t" \
        "}" \
        : "=r"(_done) : "r"(_mbar), "r"(_parity) : "memory"); \
    if (!_done) { \
        asm volatile( \
            "{\n\t" \
            ".reg .pred P1;\n\t" \
            "WAIT_LOOP_%=:\n\t" \
            "mbarrier.try_wait.parity.acquire.cta.shared::cta.b64 P1, [%0], %1, 0x989680;\n\t" \
            "@P1 bra.uni WAIT_DONE_%=;\n\t" \
            "bra.uni WAIT_LOOP_%=;\n\t" \
            "WAIT_DONE_%=:\n\t" \
            "}" \
            :: "r"(_mbar), "r"(_parity) : "memory"); \
    } \
} while (0)

// Relaxed wait: safe ONLY when all post-wait accesses are async-proxy
// (cp.async issues) — the producer path here.
#define MBARRIER_WAIT_PARITY_RELAXED(mbar_smem_addr, phase_parity) do { \
    uint32_t _mbar = (uint32_t)(mbar_smem_addr); \
    uint32_t _parity = (uint32_t)(phase_parity); \
    uint32_t _done; \
    asm volatile( \
        "{\n\t" \
        ".reg .pred p;\n\t" \
        "mbarrier.try_wait.parity.relaxed.cta.shared::cta.b64 p, [%1], %2;\n\t" \
        "selp.b32 %0, 1, 0, p;\n\t" \
        "}" \
        : "=r"(_done) : "r"(_mbar), "r"(_parity) : "memory"); \
    if (!_done) { \
        asm volatile( \
            "{\n\t" \
            ".reg .pred P1;\n\t" \
            "WAIT_LOOP_%=:\n\t" \
            "mbarrier.try_wait.parity.relaxed.cta.shared::cta.b64 P1, [%0], %1, 0x989680;\n\t" \
            "@P1 bra.uni WAIT_DONE_%=;\n\t" \
            "bra.uni WAIT_LOOP_%=;\n\t" \
            "WAIT_DONE_%=:\n\t" \
            "}" \
            :: "r"(_mbar), "r"(_parity) : "memory"); \
    } \
} while (0)

__device__ __forceinline__ void ldsm_x4(uint32_t& r0, uint32_t& r1,
                                        uint32_t& r2, uint32_t& r3, uint32_t addr) {
    asm volatile("ldmatrix.sync.aligned.m8n8.x4.shared.b16 {%0,%1,%2,%3}, [%4];"
                 : "=r"(r0), "=r"(r1), "=r"(r2), "=r"(r3) : "r"(addr));
}

__device__ __forceinline__ void mma16816(float* c, const uint32_t* a, const uint32_t* b) {
    asm volatile(
        "mma.sync.aligned.m16n8k16.row.col.f32.f16.f16.f32 "
        "{%0,%1,%2,%3}, {%4,%5,%6,%7}, {%8,%9}, {%0,%1,%2,%3};"
        : "+f"(c[0]), "+f"(c[1]), "+f"(c[2]), "+f"(c[3])
        : "r"(a[0]), "r"(a[1]), "r"(a[2]), "r"(a[3]), "r"(b[0]), "r"(b[1]));
}

// Streaming 8B store: output is write-once, never re-read by this launch.
__device__ __forceinline__ void stg_cs_f2(float* p, float2 v) {
    asm volatile("st.global.cs.v2.f32 [%0], {%1, %2};"
                 :: "l"(p), "f"(v.x), "f"(v.y) : "memory");
}

// ============================================================================
// GEMM: out[M,N] = A[M,K] * B[N,K]^T * scale[n] + bias[n]
//   R13/R15 champion pipeline, unchanged. Only delta: .cs epilogue stores.
// ============================================================================
__global__ void __launch_bounds__(THREADS, 2) gemm_kernel(
    const float* __restrict__ scales,
    const float* __restrict__ bias,
    float* __restrict__ out)
{
    extern __shared__ char smem[];
    const uint32_t sb = smem_u32(smem);
    const int tid = threadIdx.x;
    const int lane = tid & 31;
    const int wid = tid >> 5;
    const int wm = wid >> 2;       // 0..1
    const int wn = wid & 3;        // 0..3

    // CTA swizzle for L2 reuse
    constexpr int TILES_N = D_OUT / N_TILE;   // 32
    constexpr int GROUP = 8;
    const int bid = blockIdx.x;
    const int r = bid % (GROUP * TILES_N);
    const int tile_m = (bid / (GROUP * TILES_N)) * GROUP + (r % GROUP);
    const int tile_n = r / GROUP;
    const int row0 = tile_m * M_TILE;
    const int col0 = tile_n * N_TILE;

    // ---- barrier init ----
    if (tid == 0) {
        #pragma unroll
        for (int s = 0; s < STAGES; s++) {
            MBARRIER_INIT(sb + SMEM_BARS + s * 16, THREADS);  // full: 256 cp arrivals
            MBARRIER_INIT(sb + SMEM_BARS + s * 16 + 8, 8);    // empty: 8 warp arrivals
        }
    }
    __syncthreads();

    // ---- precomputed producer addressing ----
    const int trow = tid >> 3;
    const int tc16 = tid & 7;
    const __half* pA = g_A + (size_t)(row0 + trow) * D_IN + tc16 * 8;
    const __half* pB = g_B + (size_t)(col0 + trow) * D_IN + tc16 * 8;
    const uint32_t doff = (uint32_t)(trow * 128) +
                          (((uint32_t)tc16 * 16) ^ (((uint32_t)(trow & 7)) << 4));

    auto issue_A = [&](const __half* srcA, int stage) {
        const uint32_t dA = sb + SMEM_TILES + stage * STAGE_BYTES + doff;
        #pragma unroll
        for (int j = 0; j < 4; j++)
            cp_async16(dA + j * 4096, srcA + (size_t)j * 32 * D_IN);
    };
    auto issue_B = [&](const __half* srcB, int stage) {
        const uint32_t dB = sb + SMEM_TILES + stage * STAGE_BYTES + A_BYTES + doff;
        #pragma unroll
        for (int j = 0; j < 4; j++)
            cp_async16(dB + j * 4096, srcB + (size_t)j * 32 * D_IN);
    };

    // ---- prologue: fill stages 0,1; arrive on full when done ----
    #pragma unroll
    for (int s = 0; s < STAGES - 1; s++) {
        issue_A(pA + s * K_TILE, s);
        issue_B(pB + s * K_TILE, s);
        CP_ASYNC_MBAR_ARRIVE_NOINC(sb + SMEM_BARS + s * 16);
    }

    // ---- per-thread ldmatrix base addresses (verified layout) ----
    const uint32_t xm    = (lane & 7) << 4;
    const uint32_t xm_hi = xm & 0x60;
    const uint32_t xm_lo = xm & 0x10;

    uint32_t aBase[4];
    {
        uint32_t colp = ((uint32_t)(lane >> 4) << 4) ^ xm_lo;
        #pragma unroll
        for (int m = 0; m < 4; m++)
            aBase[m] = (uint32_t)((wm * 64 + m * 16 + (lane & 15)) * 128) + colp;
    }
    uint32_t bBase[2];
    {
        uint32_t colp = (((uint32_t)(lane >> 3) & 1) << 4) ^ xm_lo;
        uint32_t rowB = (uint32_t)(wn * 32 + ((lane >> 4) << 3) + (lane & 7));
        #pragma unroll
        for (int ch = 0; ch < 2; ch++)
            bBase[ch] = (rowB + ch * 16) * 128 + colp;
    }

    float acc[4][4][4];
    #pragma unroll
    for (int m = 0; m < 4; m++)
        #pragma unroll
        for (int n = 0; n < 4; n++)
            #pragma unroll
            for (int v = 0; v < 4; v++) acc[m][n][v] = 0.0f;

    // ---- main loop: per-warp pipeline, unrolled by STAGES ----
    const __half* srcA = pA + (STAGES - 1) * K_TILE;
    const __half* srcB = pB + (STAGES - 1) * K_TILE;
    int ps = STAGES - 1, pp = 1;   // producer cursor
    int fs = 0, fp = 0;            // consumer cursor
    #pragma unroll 3
    for (int kc = 0; kc < NUM_K; kc++) {
        // consumer: wait until all 256 threads' loads for this stage landed
        MBARRIER_WAIT_PARITY(sb + SMEM_BARS + fs * 16, fp);

        const uint32_t sA  = sb + SMEM_TILES + fs * STAGE_BYTES;
        const uint32_t sBb = sA + A_BYTES;

        auto do_loads = [&](int ks, uint32_t (&a)[4][4], uint32_t (&b)[4][2]) {
            const uint32_t kofs = ((uint32_t)(ks * 32)) ^ xm_hi;
            #pragma unroll
            for (int m = 0; m < 4; m++)
                ldsm_x4(a[m][0], a[m][1], a[m][2], a[m][3], sA + aBase[m] + kofs);
            #pragma unroll
            for (int ch = 0; ch < 2; ch++) {
                uint32_t r0, r1, r2, r3;
                ldsm_x4(r0, r1, r2, r3, sBb + bBase[ch] + kofs);
                b[ch * 2 + 0][0] = r0; b[ch * 2 + 0][1] = r1;
                b[ch * 2 + 1][0] = r2; b[ch * 2 + 1][1] = r3;
            }
        };
        auto do_mma = [&](uint32_t (&a)[4][4], uint32_t (&b)[4][2]) {
            #pragma unroll
            for (int m = 0; m < 4; m++)
                #pragma unroll
                for (int n = 0; n < 4; n++)
                    mma16816(acc[m][n], a[m], b[n]);
        };

        const bool refill = (kc + STAGES - 1 < NUM_K);
        uint32_t a[4][4];
        uint32_t b[4][2];

        // ks=0: stage-start LSU window serves only LDSMs
        do_loads(0, a, b); do_mma(a, b);

        // producer half 1: A tile of chunk kc+2
        if (refill) {
            MBARRIER_WAIT_PARITY_RELAXED(sb + SMEM_BARS + ps * 16 + 8, pp);
            issue_A(srcA, ps);
        }

        do_loads(1, a, b); do_mma(a, b);

        // producer half 2: B tile + completion arrive (covers both halves)
        if (refill) {
            issue_B(srcB, ps);
            CP_ASYNC_MBAR_ARRIVE_NOINC(sb + SMEM_BARS + ps * 16);
            srcA += K_TILE;
            srcB += K_TILE;
        }
        if (++ps == STAGES) { ps = 0; pp ^= 1; }

        do_loads(2, a, b); do_mma(a, b);

        // ks=3: loads, EARLY stage release (smem reads done), then MMAs
        do_loads(3, a, b);
        if (lane == 0)
            MBARRIER_ARRIVE(sb + SMEM_BARS + fs * 16 + 8);
        do_mma(a, b);

        if (++fs == STAGES) { fs = 0; fp ^= 1; }
    }

    // ---- epilogue: acc * scale[col] + bias[col], streaming stores ----
    const int cbase = col0 + wn * 32 + (lane & 3) * 2;
    float2 sc[4], bi[4];
    #pragma unroll
    for (int n = 0; n < 4; n++) {
        sc[n] = __ldg(reinterpret_cast<const float2*>(scales + cbase + n * 8));
        bi[n] = __ldg(reinterpret_cast<const float2*>(bias   + cbase + n * 8));
    }
    const int rbase = row0 + wm * 64 + (lane >> 2);
    #pragma unroll
    for (int m = 0; m < 4; m++) {
        #pragma unroll
        for (int n = 0; n < 4; n++) {
            const size_t o0 = (size_t)(rbase + m * 16) * D_OUT + cbase + n * 8;
            const size_t o1 = o0 + 8 * D_OUT;
            float2 v0, v1;
            v0.x = fmaf(acc[m][n][0], sc[n].x, bi[n].x);
            v0.y = fmaf(acc[m][n][1], sc[n].y, bi[n].y);
            v1.x = fmaf(acc[m][n][2], sc[n].x, bi[n].x);
            v1.y = fmaf(acc[m][n][3], sc[n].y, bi[n].y);
            stg_cs_f2(out + o0, v0);
            stg_cs_f2(out + o1, v1);
        }
    }
}

// ============================================================================
// Host
// ============================================================================
extern "C" void kernel_launch(void* const* d_in, const int* in_sizes, int n_in,
                              void* d_out, int out_size)
{
    const float* x  = (const float*)d_in[0];
    const int*   wq = (const int*)  d_in[1];
    const float* sc = (const float*)d_in[2];
    const float* bi = (const float*)d_in[3];
    float* out = (float*)d_out;

    prep_kernel<<<4096, 256>>>(x, wq);

    cudaFuncSetAttribute(gemm_kernel, cudaFuncAttributeMaxDynamicSharedMemorySize,
                         SMEM_TOTAL);

    const int grid = (TOKENS / M_TILE) * (D_OUT / N_TILE);  // 2048
    gemm_kernel<<<grid, THREADS, SMEM_TOTAL>>>(sc, bi, out);
}